// round 5
// baseline (speedup 1.0000x reference)
#include <cuda_runtime.h>
#include <cuda_bf16.h>
#include <cstdint>

// ForMicroLoss: loss = sum_{t==1} softplus(-p)/n_pos + sum_{t==0} softplus(p)/n_neg
// 64M elems, 512 MB read, HBM-bound. Algebra:
//   S = sum softplus(p), T = sum t*softplus(p), P = sum t*p, np = sum t
//   pos_term = T - P   (since softplus(-p) = softplus(p) - p)
//   neg_term = S - T
//   loss = (T-P)/np + (S-T)/(n-np)

#define GRID1  1184    // 148 SMs * 8 blocks
#define BLOCK1 512

__device__ float g_S[GRID1];
__device__ float g_T[GRID1];
__device__ float g_P[GRID1];
__device__ int   g_np[GRID1];
__device__ unsigned int g_count;   // zero-init; reset at end of each replay

__device__ __forceinline__ float softplus_fast(float p) {
    // softplus(p) = max(p,0) + log(1 + exp(-|p|))
    float e = __expf(-fabsf(p));
    return fmaxf(p, 0.0f) + __logf(1.0f + e);
}

struct Acc {
    float S, T, P;
    int np;
    __device__ __forceinline__ void add(float p, int t) {
        float sp = softplus_fast(p);
        float ft = (float)t;
        S += sp;
        T = fmaf(ft, sp, T);
        P = fmaf(ft, p,  P);
        np += t;
    }
    __device__ __forceinline__ void merge(const Acc& o) {
        S += o.S; T += o.T; P += o.P; np += o.np;
    }
};

__device__ __forceinline__ void acc4(Acc& a, const float4& p, const int4& t) {
    a.add(p.x, t.x);
    a.add(p.y, t.y);
    a.add(p.z, t.z);
    a.add(p.w, t.w);
}

__global__ __launch_bounds__(BLOCK1)
void fml_kernel(const float4* __restrict__ pred4,
                const int4*  __restrict__ true4,
                int n4,
                const float* __restrict__ pred,
                const int* __restrict__ truth,
                int n,
                float* __restrict__ out) {
    Acc a0 = {0.f, 0.f, 0.f, 0};
    Acc a1 = {0.f, 0.f, 0.f, 0};

    const int stride = gridDim.x * blockDim.x;
    const int tid0 = blockIdx.x * blockDim.x + threadIdx.x;

    // Unroll x4: front-batch 8 independent 16B streaming loads.
    int i = tid0;
    for (; i + 3 * stride < n4; i += 4 * stride) {
        float4 p0 = __ldcs(&pred4[i]);
        float4 p1 = __ldcs(&pred4[i +     stride]);
        float4 p2 = __ldcs(&pred4[i + 2 * stride]);
        float4 p3 = __ldcs(&pred4[i + 3 * stride]);
        int4   t0 = __ldcs(&true4[i]);
        int4   t1 = __ldcs(&true4[i +     stride]);
        int4   t2 = __ldcs(&true4[i + 2 * stride]);
        int4   t3 = __ldcs(&true4[i + 3 * stride]);
        acc4(a0, p0, t0);
        acc4(a1, p1, t1);
        acc4(a0, p2, t2);
        acc4(a1, p3, t3);
    }
    for (; i < n4; i += stride) {
        float4 p0 = __ldcs(&pred4[i]);
        int4   t0 = __ldcs(&true4[i]);
        acc4(a0, p0, t0);
    }

    // Scalar tail (n % 4 != 0 — not hit for 64M, kept for safety).
    for (int j = n4 * 4 + tid0; j < n; j += stride) {
        a1.add(pred[j], truth[j]);
    }

    a0.merge(a1);
    float S = a0.S, T = a0.T, P = a0.P;
    int np = a0.np;

    // Warp reduction.
    #pragma unroll
    for (int off = 16; off > 0; off >>= 1) {
        S  += __shfl_down_sync(0xffffffffu, S,  off);
        T  += __shfl_down_sync(0xffffffffu, T,  off);
        P  += __shfl_down_sync(0xffffffffu, P,  off);
        np += __shfl_down_sync(0xffffffffu, np, off);
    }

    __shared__ float s_S[BLOCK1 / 32];
    __shared__ float s_T[BLOCK1 / 32];
    __shared__ float s_P[BLOCK1 / 32];
    __shared__ int   s_np[BLOCK1 / 32];

    int wid  = threadIdx.x >> 5;
    int lane = threadIdx.x & 31;
    if (lane == 0) { s_S[wid] = S; s_T[wid] = T; s_P[wid] = P; s_np[wid] = np; }
    __syncthreads();

    __shared__ bool s_last;
    if (threadIdx.x == 0) {
        float bS = 0.f, bT = 0.f, bP = 0.f; int bnp = 0;
        #pragma unroll
        for (int w = 0; w < BLOCK1 / 32; w++) {
            bS += s_S[w]; bT += s_T[w]; bP += s_P[w]; bnp += s_np[w];
        }
        g_S[blockIdx.x] = bS;
        g_T[blockIdx.x] = bT;
        g_P[blockIdx.x] = bP;
        g_np[blockIdx.x] = bnp;
        __threadfence();
        unsigned int done = atomicAdd(&g_count, 1u);
        s_last = (done == (unsigned)(gridDim.x - 1));
    }
    __syncthreads();

    if (!s_last) return;

    // ---- Last block: deterministic fixed-order final reduction in double ----
    double dS = 0.0, dT = 0.0, dP = 0.0;
    long long dnp = 0;
    for (int k = threadIdx.x; k < GRID1; k += BLOCK1) {
        dS += (double)g_S[k];
        dT += (double)g_T[k];
        dP += (double)g_P[k];
        dnp += (long long)g_np[k];
    }

    __shared__ double sh_S[BLOCK1];
    __shared__ double sh_T[BLOCK1];
    __shared__ double sh_P[BLOCK1];
    __shared__ long long sh_np[BLOCK1];
    sh_S[threadIdx.x] = dS;
    sh_T[threadIdx.x] = dT;
    sh_P[threadIdx.x] = dP;
    sh_np[threadIdx.x] = dnp;
    __syncthreads();

    for (int s = BLOCK1 / 2; s > 0; s >>= 1) {
        if (threadIdx.x < s) {
            sh_S[threadIdx.x]  += sh_S[threadIdx.x + s];
            sh_T[threadIdx.x]  += sh_T[threadIdx.x + s];
            sh_P[threadIdx.x]  += sh_P[threadIdx.x + s];
            sh_np[threadIdx.x] += sh_np[threadIdx.x + s];
        }
        __syncthreads();
    }

    if (threadIdx.x == 0) {
        double np_d = (double)sh_np[0];
        double nn_d = (double)n - np_d;
        double pos_term = sh_T[0] - sh_P[0];
        double neg_term = sh_S[0] - sh_T[0];
        out[0] = (float)(pos_term / np_d + neg_term / nn_d);
        g_count = 0;   // reset for next graph replay
    }
}

extern "C" void kernel_launch(void* const* d_in, const int* in_sizes, int n_in,
                              void* d_out, int out_size) {
    const float* pred  = (const float*)d_in[0];
    const int*   truth = (const int*)d_in[1];
    float* out = (float*)d_out;

    int n  = in_sizes[0];
    int n4 = n >> 2;

    fml_kernel<<<GRID1, BLOCK1>>>(
        (const float4*)pred, (const int4*)truth, n4, pred, truth, n, out);
}